// round 3
// baseline (speedup 1.0000x reference)
#include <cuda_runtime.h>
#include <cstdint>

// Problem constants (match reference generator)
#define BB    8            // batch
#define HH    32
#define WW    32
#define TT    4
#define BSs   3
#define DD    768
#define HWT   (HH*WW*TT)       // 4096 cells per batch
#define NCELL (BB*HWT)         // 32768 cells total
#define CELL_F4 ((BSs*DD)/4)   // 576 float4 per cell (2304 floats)

// cell -> covering patch id (per batch). 512 KB device scratch (no allocs allowed).
__device__ int g_idmap[NCELL];

__global__ void init_idmap_kernel() {
    int i = blockIdx.x * blockDim.x + threadIdx.x;
    if (i < NCELL) g_idmap[i] = -1;
}

// One thread per patch: write pid into the s x s cells it covers.
// positions: [B, P, 4] rows (y, x, size, t). Tiling is a partition -> no conflicts.
__global__ void scatter_ids_kernel(const int* __restrict__ positions, int P) {
    int i = blockIdx.x * blockDim.x + threadIdx.x;
    if (i >= BB * P) return;
    int b = i / P;
    int p = i - b * P;
    const int* r = positions + (size_t)i * 4;
    int y = r[0], x = r[1], s = r[2], t = r[3];
    int base = b * HWT;
    for (int dy = 0; dy < s; ++dy) {
        for (int dx = 0; dx < s; ++dx) {
            int yy = y + dy, xx = x + dx;
            if (yy < HH && xx < WW) {
                g_idmap[base + ((yy * WW + xx) * TT + t)] = p;
            }
        }
    }
}

// One block per output cell. Copies BS*D floats = 576 float4, 3 per thread.
__global__ __launch_bounds__(192, 8)
void gather_kernel(const float4* __restrict__ tok, float4* __restrict__ out, int P) {
    int cell = blockIdx.x;                 // 0 .. NCELL-1, layout ((b*H+h)*W+w)*T+t
    int b = cell >> 12;                    // / HWT (4096)
    int pid = g_idmap[cell];

    float4* dst = out + (size_t)cell * CELL_F4;
    int tix = threadIdx.x;

    if (pid < 0) {
        float4 z = make_float4(0.f, 0.f, 0.f, 0.f);
        #pragma unroll
        for (int k = 0; k < 3; ++k) dst[tix + k * 192] = z;
        return;
    }

    const float4* src = tok + ((size_t)b * P + pid) * CELL_F4;
    #pragma unroll
    for (int k = 0; k < 3; ++k) {
        dst[tix + k * 192] = __ldg(&src[tix + k * 192]);
    }
}

extern "C" void kernel_launch(void* const* d_in, const int* in_sizes, int n_in,
                              void* d_out, int out_size) {
    const float4* tok = (const float4*)d_in[0];     // modality_tokens [B, P*BS, D] fp32
    const int*    pos = (const int*)d_in[1];        // positions [B, P, 4] int32

    int P = in_sizes[1] / (BB * 4);                 // 2560

    // 1) reset cell->pid map (determinism across graph replays)
    init_idmap_kernel<<<(NCELL + 255) / 256, 256>>>();

    // 2) scatter patch ids into cells
    int npatch = BB * P;
    scatter_ids_kernel<<<(npatch + 255) / 256, 256>>>(pos, P);

    // 3) gather: one block per output cell, fully coalesced float4 copy
    gather_kernel<<<NCELL, 192>>>(tok, (float4*)d_out, P);
}

// round 4
// speedup vs baseline: 1.0458x; 1.0458x over previous
#include <cuda_runtime.h>
#include <cstdint>

// Problem constants (match reference generator)
#define BB    8            // batch
#define HH    32
#define WW    32
#define TT    4
#define BSs   3
#define DD    768
#define HWT   (HH*WW*TT)       // 4096 cells per batch
#define CELL_F4 ((BSs*DD)/4)   // 576 float4 per cell (2304 floats)
#define THREADS 192            // 3 float4 per thread

// Patch-centric: one block per patch. Load the patch token once into
// registers, store it to every (s x s) cell the patch covers.
// Output layout: [B, H, W, T, BS, D] -> cell index ((b*H+y)*W+x)*T+t.
// The position tiling is a partition of the grid, so every output cell is
// written exactly once per launch (fully deterministic across graph replays,
// no init pass needed).
__global__ __launch_bounds__(THREADS, 8)
void apt_expand_kernel(const float4* __restrict__ tok,
                       const int*    __restrict__ positions,
                       float4*       __restrict__ out,
                       int P) {
    int i = blockIdx.x;                    // patch index over B*P
    int b = i / P;
    int tix = threadIdx.x;

    const int4 r = __ldg((const int4*)(positions + (size_t)i * 4));
    const int y = r.x, x = r.y, s = r.z, t = r.w;

    // Load this patch's 2304 floats once (coalesced, 3 float4 per thread)
    const float4* src = tok + (size_t)i * CELL_F4;
    float4 v0 = __ldg(&src[tix]);
    float4 v1 = __ldg(&src[tix + THREADS]);
    float4 v2 = __ldg(&src[tix + 2 * THREADS]);

    // Store to each covered cell (s is 1 or 2)
    const size_t base_cell = ((size_t)b * HH + y) * WW + x;
    for (int dy = 0; dy < s; ++dy) {
        for (int dx = 0; dx < s; ++dx) {
            size_t cell = ((base_cell + (size_t)dy * WW + dx) * TT + t);
            float4* dst = out + cell * CELL_F4;
            dst[tix]               = v0;
            dst[tix + THREADS]     = v1;
            dst[tix + 2 * THREADS] = v2;
        }
    }
}

extern "C" void kernel_launch(void* const* d_in, const int* in_sizes, int n_in,
                              void* d_out, int out_size) {
    const float4* tok = (const float4*)d_in[0];     // modality_tokens [B, P*BS, D] fp32
    const int*    pos = (const int*)d_in[1];        // positions [B, P, 4] int32

    int P = in_sizes[1] / (BB * 4);                 // 2560

    apt_expand_kernel<<<BB * P, THREADS>>>(tok, pos, (float4*)d_out, P);
}

// round 5
// speedup vs baseline: 1.0471x; 1.0013x over previous
#include <cuda_runtime.h>
#include <cstdint>

// Problem constants (match reference generator)
#define BB    8            // batch
#define HH    32
#define WW    32
#define TT    4
#define BSs   3
#define DD    768
#define CELL_F4 ((BSs*DD)/4)   // 576 float4 per cell (2304 floats)
#define THREADS 192            // 3 float4 per thread

// Patch-centric: one block per patch. Load the patch token once into
// registers (streaming, no reuse), store it to every (s x s) cell it covers
// (streaming stores, output is never re-read).
// Output layout: [B, H, W, T, BS, D] -> cell index ((b*H+y)*W+x)*T+t.
// The position tiling is a partition of the grid, so every output cell is
// written exactly once per launch (deterministic across graph replays).
__global__ __launch_bounds__(THREADS, 10)
void apt_expand_kernel(const float4* __restrict__ tok,
                       const int*    __restrict__ positions,
                       float4*       __restrict__ out,
                       int P) {
    const int i = blockIdx.x;              // patch index over B*P
    const int b = i / P;
    const int tix = threadIdx.x;

    const int4 r = __ldg((const int4*)(positions + (size_t)i * 4));
    const int y = r.x, x = r.y, s = r.z, t = r.w;

    // Load this patch's 2304 floats once (coalesced, streaming: no reuse)
    const float4* src = tok + (size_t)i * CELL_F4;
    const float4 v0 = __ldcs(&src[tix]);
    const float4 v1 = __ldcs(&src[tix + THREADS]);
    const float4 v2 = __ldcs(&src[tix + 2 * THREADS]);

    // Store to each covered cell (s is 1 or 2); evict-first streaming stores
    const size_t base_cell = ((size_t)b * HH + y) * WW + x;
    #pragma unroll 1
    for (int dy = 0; dy < s; ++dy) {
        #pragma unroll 1
        for (int dx = 0; dx < s; ++dx) {
            const size_t cell = (base_cell + (size_t)dy * WW + dx) * TT + t;
            float4* dst = out + cell * CELL_F4;
            __stcs(&dst[tix],               v0);
            __stcs(&dst[tix + THREADS],     v1);
            __stcs(&dst[tix + 2 * THREADS], v2);
        }
    }
}

extern "C" void kernel_launch(void* const* d_in, const int* in_sizes, int n_in,
                              void* d_out, int out_size) {
    const float4* tok = (const float4*)d_in[0];     // modality_tokens [B, P*BS, D] fp32
    const int*    pos = (const int*)d_in[1];        // positions [B, P, 4] int32

    int P = in_sizes[1] / (BB * 4);                 // 2560

    apt_expand_kernel<<<BB * P, THREADS>>>(tok, pos, (float4*)d_out, P);
}